// round 8
// baseline (speedup 1.0000x reference)
#include <cuda_runtime.h>
#include <cstdint>

#define NN 20000
#define NE 320000
#define H 128
#define DE 32
#define NL 4
#define ETILE 128               // edges per tile in k_edge
#define NTILES (NE / ETILE)     // 2500

// ---------------- scratch (device globals) -----------------------------------
__device__ float g_radial[NE];
__device__ float g_P[NN * H];
__device__ float g_Q[NN * H];
__device__ float g_agg[NN * H];
__device__ float g_h[NN * H];
__device__ float g_ew1t[NL * 289 * H];
__device__ float g_w2t[NL * H * H];
__device__ float g_nw1t[NL * 2 * H * H];
__device__ float g_nw2t[NL * H * H];

// ---------------- helpers -----------------------------------------------------
__device__ __forceinline__ float siluf(float x) {
    return x * (1.0f / (1.0f + __expf(-x)));
}
__device__ __forceinline__ float4 add4(float4 a, float4 b) {
    return make_float4(a.x + b.x, a.y + b.y, a.z + b.z, a.w + b.w);
}
__device__ __forceinline__ float4 silu4(float4 v) {
    v.x = siluf(v.x); v.y = siluf(v.y); v.z = siluf(v.z); v.w = siluf(v.w);
    return v;
}
__device__ __forceinline__ float tf32r(float x) {
    unsigned int u;
    asm("cvt.rna.tf32.f32 %0, %1;" : "=r"(u) : "f"(x));
    return __uint_as_float(u);
}
__device__ __forceinline__ unsigned int fb(float x) { return __float_as_uint(x); }

__device__ __forceinline__ void mma8(float* d, unsigned int a0, unsigned int a1,
                                     unsigned int a2, unsigned int a3,
                                     unsigned int b0, unsigned int b1) {
    asm volatile(
        "mma.sync.aligned.m16n8k8.row.col.f32.tf32.tf32.f32 "
        "{%0,%1,%2,%3},{%4,%5,%6,%7},{%8,%9},{%0,%1,%2,%3};\n"
        : "+f"(d[0]), "+f"(d[1]), "+f"(d[2]), "+f"(d[3])
        : "r"(a0), "r"(a1), "r"(a2), "r"(a3), "r"(b0), "r"(b1));
}

// ---------------- prep: copy h, zero agg, radial (one launch) ------------------
__global__ void k_prep(const float* __restrict__ h, const float* __restrict__ coords,
                       const int* __restrict__ edges) {
    int i = blockIdx.x * blockDim.x + threadIdx.x;   // 640000 threads
    ((float4*)g_h)[i] = ((const float4*)h)[i];
    ((float4*)g_agg)[i] = make_float4(0.f, 0.f, 0.f, 0.f);
    if (i < NE) {
        int r = edges[i], c = edges[NE + i];
        float dx = coords[3 * r]     - coords[3 * c];
        float dy = coords[3 * r + 1] - coords[3 * c + 1];
        float dz = coords[3 * r + 2] - coords[3 * c + 2];
        g_radial[i] = dx * dx + dy * dy + dz * dz;
    }
}

// single launch: convert all weight tensors to tf32-rounded copies
__global__ void k_cvt_all(const float* __restrict__ ew1, const float* __restrict__ ew2,
                          const float* __restrict__ nw1, const float* __restrict__ nw2) {
    int t0 = blockIdx.x * blockDim.x + threadIdx.x;
    int stride = gridDim.x * blockDim.x;
    for (int i = t0; i < NL * 289 * H; i += stride) g_ew1t[i] = tf32r(ew1[i]);
    for (int i = t0; i < NL * H * H; i += stride)   g_w2t[i]  = tf32r(ew2[i]);
    for (int i = t0; i < NL * 2 * H * H; i += stride) g_nw1t[i] = tf32r(nw1[i]);
    for (int i = t0; i < NL * H * H; i += stride)   g_nw2t[i] = tf32r(nw2[i]);
}

// ---------------- k_pq: P = h @ W1a, Q = h @ W1b (tf32 mma) -------------------
#define PQ_SMEM ((64 * 132 + 128 * 132) * 4)
__global__ __launch_bounds__(256) void k_pq(int lyr) {
    extern __shared__ float sm[];
    float* As = sm;                 // [64][132]
    float* Bs = sm + 64 * 132;      // [128][132]
    int tid = threadIdx.x;
    int m0 = blockIdx.x * 64;
    const float* B = g_ew1t + (size_t)lyr * 289 * H + (size_t)blockIdx.y * H * H;
    float* C = blockIdx.y ? g_Q : g_P;

#pragma unroll
    for (int i = 0; i < 8; i++) {
        int id = tid + 256 * i;
        int r = id >> 5, cv = id & 31;
        int n = m0 + r;
        float4 v = (n < NN) ? ((const float4*)(g_h + (size_t)n * H))[cv]
                            : make_float4(0.f, 0.f, 0.f, 0.f);
        v.x = tf32r(v.x); v.y = tf32r(v.y); v.z = tf32r(v.z); v.w = tf32r(v.w);
        ((float4*)(As + r * 132))[cv] = v;
    }
#pragma unroll
    for (int i = 0; i < 16; i++) {
        int id = tid + 256 * i;
        int r = id >> 5, cv = id & 31;
        ((float4*)(Bs + r * 132))[cv] = ((const float4*)(B + (size_t)r * H))[cv];
    }
    __syncthreads();

    int wid = tid >> 5, lane = tid & 31;
    int warpM = wid & 3, warpN = wid >> 2;
    int g = lane >> 2, t = lane & 3;
    int r0 = warpM * 16, n0 = warpN * 64;
    const float* A0 = As + (r0 + g) * 132;
    const float* A1 = As + (r0 + g + 8) * 132;
    const float* Bp = Bs + t * 132 + n0 + g;

    float acc[8][4];
#pragma unroll
    for (int nf = 0; nf < 8; nf++)
#pragma unroll
        for (int j = 0; j < 4; j++) acc[nf][j] = 0.f;

#pragma unroll
    for (int k0 = 0; k0 < 128; k0 += 8) {
        unsigned int a0 = fb(A0[k0 + t]),     a1 = fb(A1[k0 + t]);
        unsigned int a2 = fb(A0[k0 + t + 4]), a3 = fb(A1[k0 + t + 4]);
#pragma unroll
        for (int nf = 0; nf < 8; nf++) {
            unsigned int b0 = fb(Bp[k0 * 132 + nf * 8]);
            unsigned int b1 = fb(Bp[(k0 + 4) * 132 + nf * 8]);
            mma8(acc[nf], a0, a1, a2, a3, b0, b1);
        }
    }
    int ng  = m0 + r0 + g;
    int ng8 = ng + 8;
#pragma unroll
    for (int nf = 0; nf < 8; nf++) {
        int col = n0 + nf * 8 + 2 * t;
        if (ng < NN)
            *(float2*)(C + (size_t)ng * H + col)  = make_float2(acc[nf][0], acc[nf][1]);
        if (ng8 < NN)
            *(float2*)(C + (size_t)ng8 * H + col) = make_float2(acc[nf][2], acc[nf][3]);
    }
}

// ---------------- k_edge: persistent + fragment-major weight layout ------------
// 148 blocks x 512 threads; tiles of 128 edges.
// W1c/W2 stored in smem permuted so each lane's 8 B-values per k-row are
// contiguous: Wv[k][half*64 + g*8 + nf] = W[k][half*64 + nf*8 + g]
// -> 2 float4 LDS per k-row instead of 8 scalar LDS.
#define EDGE_SMEM ((128 * 44 + 40 * 132 + 128 * 132 + 128 * 132) * 4 + 2 * ETILE * 4)

__global__ __launch_bounds__(512, 1) void k_edge(
    const int* __restrict__ edges, const float* __restrict__ edge_attr,
    const float* __restrict__ eb1, const float* __restrict__ eb2, int lyr) {
    extern __shared__ float sm[];
    float* xs   = sm;                               // [128][44]
    float* W1cs = sm + 128 * 44;                    // [40][132]  (permuted)
    float* Sh   = W1cs + 40 * 132;                  // [128][132]
    float* W2s  = Sh + 128 * 132;                   // [128][132] (permuted)
    int*   rs   = (int*)(W2s + 128 * 132);          // [128]
    int*   cs   = rs + ETILE;

    int tid = threadIdx.x;

    // ---- stage W1c (perm, rows 0..32 real, 33..39 zero) and W2 (perm), once
    {
        const float* W1c = g_ew1t + (size_t)lyr * 289 * H + 256 * H;
#pragma unroll
        for (int i = 0; i < 3; i++) {
            int id = tid + 512 * i;
            if (id < 33 * 32) {
                int r = id >> 5, cv = id & 31;
                float4 v = ((const float4*)(W1c + (size_t)r * H))[cv];
                int c0 = cv * 4;
                int half = c0 >> 6, w0 = c0 & 63;
                float* dst = W1cs + r * 132 + (half << 6) + (w0 >> 3);
                int gb = w0 & 7;
                dst[(gb + 0) * 8] = v.x; dst[(gb + 1) * 8] = v.y;
                dst[(gb + 2) * 8] = v.z; dst[(gb + 3) * 8] = v.w;
            }
        }
#pragma unroll
        for (int i = 0; i < 2; i++) {
            int id = tid + 512 * i;
            if (id < 7 * 128) W1cs[(33 + (id >> 7)) * 132 + (id & 127)] = 0.f;
        }
        const float* W2 = g_w2t + (size_t)lyr * H * H;
#pragma unroll
        for (int i = 0; i < 8; i++) {
            int id = tid + 512 * i;
            int r = id >> 5, cv = id & 31;
            float4 v = ((const float4*)(W2 + (size_t)r * H))[cv];
            int c0 = cv * 4;
            int half = c0 >> 6, w0 = c0 & 63;
            float* dst = W2s + r * 132 + (half << 6) + (w0 >> 3);
            int gb = w0 & 7;
            dst[(gb + 0) * 8] = v.x; dst[(gb + 1) * 8] = v.y;
            dst[(gb + 2) * 8] = v.z; dst[(gb + 3) * 8] = v.w;
        }
    }

    int wid = tid >> 5, lane = tid & 31;
    int warpM = wid & 7, warpN = wid >> 3;          // 8 M-groups x 2 N-groups
    int g = lane >> 2, t = lane & 3;
    int r0 = warpM * 16, n0 = warpN * 64;

    for (int tile = blockIdx.x; tile < NTILES; tile += gridDim.x) {
        int e0 = tile * ETILE;
        __syncthreads();   // prior tile's phase2 reads / phase3 rs reads done

        // ---- stage X for this tile
        if (tid < ETILE) {
            rs[tid] = edges[e0 + tid];
            cs[tid] = edges[NE + e0 + tid];
            xs[tid * 44] = tf32r(g_radial[e0 + tid]);
#pragma unroll
            for (int j = 33; j < 40; j++) xs[tid * 44 + j] = 0.f;
        }
#pragma unroll
        for (int i = 0; i < 2; i++) {               // edge_attr: 128 x 8 float4
            int id = tid + 512 * i;
            int e = id >> 3, cv = id & 7;
            float4 v = ((const float4*)(edge_attr + (size_t)(e0 + e) * DE))[cv];
            float* xp = xs + e * 44 + 1 + cv * 4;
            xp[0] = tf32r(v.x); xp[1] = tf32r(v.y); xp[2] = tf32r(v.z); xp[3] = tf32r(v.w);
        }
        __syncthreads();

        // ---- phase 1: X @ W1c (K=40) + bias + P/Q gathers + silu -> Sh
        {
            float acc[8][4];
#pragma unroll
            for (int nf = 0; nf < 8; nf++) {
                float2 b = *(const float2*)(eb1 + n0 + nf * 8 + 2 * t);
                acc[nf][0] = b.x; acc[nf][1] = b.y; acc[nf][2] = b.x; acc[nf][3] = b.y;
            }
            const float* A0 = xs + (r0 + g) * 44;
            const float* A1 = A0 + 8 * 44;
#pragma unroll
            for (int k0 = 0; k0 < 40; k0 += 8) {
                unsigned int a0 = fb(A0[k0 + t]),     a1 = fb(A1[k0 + t]);
                unsigned int a2 = fb(A0[k0 + t + 4]), a3 = fb(A1[k0 + t + 4]);
                const float* rA = W1cs + (k0 + t) * 132 + n0 + g * 8;
                const float* rB = W1cs + (k0 + t + 4) * 132 + n0 + g * 8;
                float4 v0 = *(const float4*)rA;
                float4 v2 = *(const float4*)rB;
                mma8(acc[0], a0, a1, a2, a3, fb(v0.x), fb(v2.x));
                mma8(acc[1], a0, a1, a2, a3, fb(v0.y), fb(v2.y));
                mma8(acc[2], a0, a1, a2, a3, fb(v0.z), fb(v2.z));
                mma8(acc[3], a0, a1, a2, a3, fb(v0.w), fb(v2.w));
                float4 v1 = *(const float4*)(rA + 4);
                float4 v3 = *(const float4*)(rB + 4);
                mma8(acc[4], a0, a1, a2, a3, fb(v1.x), fb(v3.x));
                mma8(acc[5], a0, a1, a2, a3, fb(v1.y), fb(v3.y));
                mma8(acc[6], a0, a1, a2, a3, fb(v1.z), fb(v3.z));
                mma8(acc[7], a0, a1, a2, a3, fb(v1.w), fb(v3.w));
            }
            int rA = rs[r0 + g], rB = rs[r0 + g + 8];
            int cA = cs[r0 + g], cB = cs[r0 + g + 8];
            const float* PA = g_P + (size_t)rA * H;
            const float* QA = g_Q + (size_t)cA * H;
            const float* PB = g_P + (size_t)rB * H;
            const float* QB = g_Q + (size_t)cB * H;
            float* S0 = Sh + (r0 + g) * 132;
            float* S1 = S0 + 8 * 132;
#pragma unroll
            for (int nf = 0; nf < 8; nf++) {
                int col = n0 + nf * 8 + 2 * t;
                float2 pa = *(const float2*)(PA + col), qa = *(const float2*)(QA + col);
                float2 pb = *(const float2*)(PB + col), qb = *(const float2*)(QB + col);
                float v0 = acc[nf][0] + pa.x + qa.x;
                float v1 = acc[nf][1] + pa.y + qa.y;
                float v2 = acc[nf][2] + pb.x + qb.x;
                float v3 = acc[nf][3] + pb.y + qb.y;
                *(float2*)(S0 + col) = make_float2(tf32r(siluf(v0)), tf32r(siluf(v1)));
                *(float2*)(S1 + col) = make_float2(tf32r(siluf(v2)), tf32r(siluf(v3)));
            }
        }
        __syncthreads();

        // ---- phase 2: Sh @ W2 (K=128), vectorized B loads
        float acc2[8][4];
#pragma unroll
        for (int nf = 0; nf < 8; nf++)
#pragma unroll
            for (int j = 0; j < 4; j++) acc2[nf][j] = 0.f;
        {
            const float* A0s = Sh + (r0 + g) * 132;
            const float* A1s = A0s + 8 * 132;
#pragma unroll
            for (int k0 = 0; k0 < 128; k0 += 8) {
                unsigned int a0 = fb(A0s[k0 + t]),     a1 = fb(A1s[k0 + t]);
                unsigned int a2 = fb(A0s[k0 + t + 4]), a3 = fb(A1s[k0 + t + 4]);
                const float* rA = W2s + (k0 + t) * 132 + n0 + g * 8;
                const float* rB = W2s + (k0 + t + 4) * 132 + n0 + g * 8;
                float4 v0 = *(const float4*)rA;
                float4 v2 = *(const float4*)rB;
                mma8(acc2[0], a0, a1, a2, a3, fb(v0.x), fb(v2.x));
                mma8(acc2[1], a0, a1, a2, a3, fb(v0.y), fb(v2.y));
                mma8(acc2[2], a0, a1, a2, a3, fb(v0.z), fb(v2.z));
                mma8(acc2[3], a0, a1, a2, a3, fb(v0.w), fb(v2.w));
                float4 v1 = *(const float4*)(rA + 4);
                float4 v3 = *(const float4*)(rB + 4);
                mma8(acc2[4], a0, a1, a2, a3, fb(v1.x), fb(v3.x));
                mma8(acc2[5], a0, a1, a2, a3, fb(v1.y), fb(v3.y));
                mma8(acc2[6], a0, a1, a2, a3, fb(v1.z), fb(v3.z));
                mma8(acc2[7], a0, a1, a2, a3, fb(v1.w), fb(v3.w));
            }
        }

        // ---- phase 3: pack via shfl, bias+silu, float4 atomic scatter
        {
            bool odd = (t & 1);
            int node = odd ? rs[r0 + g + 8] : rs[r0 + g];
#pragma unroll
            for (int nf = 0; nf < 8; nf++) {
                float px = odd ? acc2[nf][0] : acc2[nf][2];
                float py = odd ? acc2[nf][1] : acc2[nf][3];
                float rx = __shfl_xor_sync(0xffffffffu, px, 1);
                float ry = __shfl_xor_sync(0xffffffffu, py, 1);
                float4 v;
                int col;
                if (!odd) {
                    v = make_float4(acc2[nf][0], acc2[nf][1], rx, ry);
                    col = n0 + nf * 8 + 2 * t;
                } else {
                    v = make_float4(rx, ry, acc2[nf][2], acc2[nf][3]);
                    col = n0 + nf * 8 + 2 * (t - 1);
                }
                float4 b = *(const float4*)(eb2 + col);
                v = silu4(add4(v, b));
                atomicAdd((float4*)(g_agg + (size_t)node * H + col), v);
            }
        }
    }
}

// ---------------- k_node: fused [h|agg]@nw1 -> silu -> @nw2 (+res) + agg-zero --
#define NODE_SMEM ((64 * 260 + 256 * 132) * 4)
__global__ __launch_bounds__(256) void k_node(
    const float* __restrict__ nb1, const float* __restrict__ nb2,
    int lyr, int residual) {
    extern __shared__ float sm[];
    float* As  = sm;                  // [64][260]; later Ss [64][132]
    float* Bs  = sm + 64 * 260;       // [256][132] nw1t; later [128][132] nw2t
    int tid = threadIdx.x;
    int m0 = blockIdx.x * 64;

#pragma unroll
    for (int i = 0; i < 16; i++) {
        int id = tid + 256 * i;
        int r = id >> 6, cv = id & 63;
        int n = m0 + r;
        const float* src = (cv < 32) ? (g_h + (size_t)n * H + cv * 4)
                                     : (g_agg + (size_t)n * H + (cv - 32) * 4);
        float4 v = (n < NN) ? *(const float4*)src : make_float4(0.f, 0.f, 0.f, 0.f);
        if (cv >= 32 && n < NN)
            *(float4*)(g_agg + (size_t)n * H + (cv - 32) * 4) = make_float4(0.f, 0.f, 0.f, 0.f);
        v.x = tf32r(v.x); v.y = tf32r(v.y); v.z = tf32r(v.z); v.w = tf32r(v.w);
        float* dst = As + r * 260 + cv * 4;
        dst[0] = v.x; dst[1] = v.y; dst[2] = v.z; dst[3] = v.w;
    }
    {
        const float* B = g_nw1t + (size_t)lyr * 2 * H * H;
#pragma unroll
        for (int i = 0; i < 32; i++) {
            int id = tid + 256 * i;
            int r = id >> 5, cv = id & 31;
            ((float4*)(Bs + r * 132))[cv] = ((const float4*)(B + (size_t)r * H))[cv];
        }
    }
    __syncthreads();

    int wid = tid >> 5, lane = tid & 31;
    int warpM = wid & 3, warpN = wid >> 2;
    int g = lane >> 2, t = lane & 3;
    int r0 = warpM * 16, n0 = warpN * 64;

    float acc[8][4];
#pragma unroll
    for (int nf = 0; nf < 8; nf++)
#pragma unroll
        for (int j = 0; j < 4; j++) acc[nf][j] = 0.f;

    {   // GEMM1: K = 256
        const float* A0 = As + (r0 + g) * 260;
        const float* A1 = As + (r0 + g + 8) * 260;
        const float* Bp = Bs + t * 132 + n0 + g;
#pragma unroll
        for (int k0 = 0; k0 < 256; k0 += 8) {
            unsigned int a0 = fb(A0[k0 + t]),     a1 = fb(A1[k0 + t]);
            unsigned int a2 = fb(A0[k0 + t + 4]), a3 = fb(A1[k0 + t + 4]);
#pragma unroll
            for (int nf = 0; nf < 8; nf++) {
                unsigned int b0 = fb(Bp[k0 * 132 + nf * 8]);
                unsigned int b1 = fb(Bp[(k0 + 4) * 132 + nf * 8]);
                mma8(acc[nf], a0, a1, a2, a3, b0, b1);
            }
        }
    }
    __syncthreads();

    {   // epilogue 1: silu(+b1) -> Ss (tf32), load Bs2
        float* Ss = As;
#pragma unroll
        for (int nf = 0; nf < 8; nf++) {
            int col = n0 + nf * 8 + 2 * t;
            float2 b = *(const float2*)(nb1 + col);
            float* s0 = Ss + (r0 + g) * 132 + col;
            float* s1 = Ss + (r0 + g + 8) * 132 + col;
            s0[0] = tf32r(siluf(acc[nf][0] + b.x));
            s0[1] = tf32r(siluf(acc[nf][1] + b.y));
            s1[0] = tf32r(siluf(acc[nf][2] + b.x));
            s1[1] = tf32r(siluf(acc[nf][3] + b.y));
        }
        const float* B = g_nw2t + (size_t)lyr * H * H;
#pragma unroll
        for (int i = 0; i < 16; i++) {
            int id = tid + 256 * i;
            int r = id >> 5, cv = id & 31;
            ((float4*)(Bs + r * 132))[cv] = ((const float4*)(B + (size_t)r * H))[cv];
        }
    }
    __syncthreads();

    {   // GEMM2: K = 128
#pragma unroll
        for (int nf = 0; nf < 8; nf++)
#pragma unroll
            for (int j = 0; j < 4; j++) acc[nf][j] = 0.f;
        const float* Ss = As;
        const float* A0 = Ss + (r0 + g) * 132;
        const float* A1 = Ss + (r0 + g + 8) * 132;
        const float* Bp = Bs + t * 132 + n0 + g;
#pragma unroll
        for (int k0 = 0; k0 < 128; k0 += 8) {
            unsigned int a0 = fb(A0[k0 + t]),     a1 = fb(A1[k0 + t]);
            unsigned int a2 = fb(A0[k0 + t + 4]), a3 = fb(A1[k0 + t + 4]);
#pragma unroll
            for (int nf = 0; nf < 8; nf++) {
                unsigned int b0 = fb(Bp[k0 * 132 + nf * 8]);
                unsigned int b1 = fb(Bp[(k0 + 4) * 132 + nf * 8]);
                mma8(acc[nf], a0, a1, a2, a3, b0, b1);
            }
        }
    }

    int ng  = m0 + r0 + g;
    int ng8 = ng + 8;
#pragma unroll
    for (int nf = 0; nf < 8; nf++) {
        int col = n0 + nf * 8 + 2 * t;
        float2 b = *(const float2*)(nb2 + col);
        if (ng < NN) {
            float2* hp = (float2*)(g_h + (size_t)ng * H + col);
            float2 o = make_float2(acc[nf][0] + b.x, acc[nf][1] + b.y);
            if (residual) { float2 old = *hp; o.x += old.x; o.y += old.y; }
            *hp = o;
        }
        if (ng8 < NN) {
            float2* hp = (float2*)(g_h + (size_t)ng8 * H + col);
            float2 o = make_float2(acc[nf][2] + b.x, acc[nf][3] + b.y);
            if (residual) { float2 old = *hp; o.x += old.x; o.y += old.y; }
            *hp = o;
        }
    }
}

// ---------------- final LayerNorm ---------------------------------------------
__global__ void k_ln(const float* __restrict__ gam, const float* __restrict__ bet,
                     float* __restrict__ out) {
    int gw = (blockIdx.x * blockDim.x + threadIdx.x) >> 5;
    int lane = threadIdx.x & 31;
    if (gw >= NN) return;
    const float* hr = g_h + (size_t)gw * H;
    float v[4];
    float s = 0.f;
#pragma unroll
    for (int j = 0; j < 4; j++) { v[j] = hr[lane + 32 * j]; s += v[j]; }
#pragma unroll
    for (int o = 16; o > 0; o >>= 1) s += __shfl_xor_sync(0xffffffffu, s, o);
    float mu = s * (1.f / 128.f);
    float vs = 0.f;
#pragma unroll
    for (int j = 0; j < 4; j++) { float d = v[j] - mu; vs += d * d; }
#pragma unroll
    for (int o = 16; o > 0; o >>= 1) vs += __shfl_xor_sync(0xffffffffu, vs, o);
    float inv = rsqrtf(vs * (1.f / 128.f) + 1e-5f);
#pragma unroll
    for (int j = 0; j < 4; j++) {
        int f = lane + 32 * j;
        out[(size_t)gw * H + f] = (v[j] - mu) * inv * gam[f] + bet[f];
    }
}

// ---------------- launch -------------------------------------------------------
extern "C" void kernel_launch(void* const* d_in, const int* in_sizes, int n_in,
                              void* d_out, int out_size) {
    const float* h   = (const float*)d_in[0];
    const float* co  = (const float*)d_in[1];
    const float* ea  = (const float*)d_in[2];
    const int*   ed  = (const int*)d_in[3];
    const float* ew1 = (const float*)d_in[4];
    const float* eb1 = (const float*)d_in[5];
    const float* ew2 = (const float*)d_in[6];
    const float* eb2 = (const float*)d_in[7];
    const float* nw1 = (const float*)d_in[8];
    const float* nb1 = (const float*)d_in[9];
    const float* nw2 = (const float*)d_in[10];
    const float* nb2 = (const float*)d_in[11];
    const float* lng = (const float*)d_in[12];
    const float* lnb = (const float*)d_in[13];
    float* out = (float*)d_out;

    cudaFuncSetAttribute(k_pq,   cudaFuncAttributeMaxDynamicSharedMemorySize, PQ_SMEM);
    cudaFuncSetAttribute(k_edge, cudaFuncAttributeMaxDynamicSharedMemorySize, EDGE_SMEM);
    cudaFuncSetAttribute(k_node, cudaFuncAttributeMaxDynamicSharedMemorySize, NODE_SMEM);

    k_prep<<<2500, 256>>>(h, co, ed);
    k_cvt_all<<<256, 512>>>(ew1, ew2, nw1, nw2);

    for (int i = 0; i < NL; i++) {
        k_pq<<<dim3(313, 2), 256, PQ_SMEM>>>(i);
        k_edge<<<148, 512, EDGE_SMEM>>>(ed, ea, eb1 + i * H, eb2 + i * H, i);
        k_node<<<313, 256, NODE_SMEM>>>(nb1 + i * H, nb2 + i * H, i, i > 0);
    }
    k_ln<<<2500, 256>>>(lng, lnb, out);
}

// round 10
// speedup vs baseline: 1.1996x; 1.1996x over previous
#include <cuda_runtime.h>
#include <cuda_fp16.h>
#include <cstdint>

#define NN 20000
#define NE 320000
#define H 128
#define DE 32
#define NL 4
#define ETILE 128               // edges per tile in k_edge
#define NTILES (NE / ETILE)     // 2500

// ---------------- scratch (device globals) -----------------------------------
__device__ float g_radial[NE];
__device__ float g_P[NN * H];
__device__ float g_Q[NN * H];
__device__ float g_agg[NN * H];
__device__ float g_h[NN * H];
__device__ float g_ew1t[NL * 289 * H];          // tf32 fp32 (k_pq)
__device__ float g_nw1t[NL * 2 * H * H];        // tf32 fp32 (k_node)
__device__ float g_nw2t[NL * H * H];            // tf32 fp32 (k_node)
// fp16, n-major, k-pair-permuted B operands for k_edge
__device__ __align__(16) __half g_w1ch[NL * 128 * 48];
__device__ __align__(16) __half g_w2h[NL * 128 * 128];

// ---------------- helpers -----------------------------------------------------
__device__ __forceinline__ float siluf(float x) {
    return x * (1.0f / (1.0f + __expf(-x)));
}
__device__ __forceinline__ float4 add4(float4 a, float4 b) {
    return make_float4(a.x + b.x, a.y + b.y, a.z + b.z, a.w + b.w);
}
__device__ __forceinline__ float4 silu4(float4 v) {
    v.x = siluf(v.x); v.y = siluf(v.y); v.z = siluf(v.z); v.w = siluf(v.w);
    return v;
}
__device__ __forceinline__ float tf32r(float x) {
    unsigned int u;
    asm("cvt.rna.tf32.f32 %0, %1;" : "=r"(u) : "f"(x));
    return __uint_as_float(u);
}
__device__ __forceinline__ unsigned int fb(float x) { return __float_as_uint(x); }

// k-permutation within each 16-block so a lane's 4 B halves are one uint2:
// lane t needs k = {2t, 2t+1, 8+2t, 8+2t+1} -> stored at {4t, 4t+1, 4t+2, 4t+3}
__device__ __forceinline__ int kperm(int k) {
    int blk = k & ~15, j = k & 15;
    int lo = j & 1, hi = j >> 3, t = (j & 7) >> 1;
    return blk + 4 * t + 2 * hi + lo;
}

__device__ __forceinline__ void mma8(float* d, unsigned int a0, unsigned int a1,
                                     unsigned int a2, unsigned int a3,
                                     unsigned int b0, unsigned int b1) {
    asm volatile(
        "mma.sync.aligned.m16n8k8.row.col.f32.tf32.tf32.f32 "
        "{%0,%1,%2,%3},{%4,%5,%6,%7},{%8,%9},{%0,%1,%2,%3};\n"
        : "+f"(d[0]), "+f"(d[1]), "+f"(d[2]), "+f"(d[3])
        : "r"(a0), "r"(a1), "r"(a2), "r"(a3), "r"(b0), "r"(b1));
}
__device__ __forceinline__ void mma16(float* d, unsigned int a0, unsigned int a1,
                                      unsigned int a2, unsigned int a3,
                                      unsigned int b0, unsigned int b1) {
    asm volatile(
        "mma.sync.aligned.m16n8k16.row.col.f32.f16.f16.f32 "
        "{%0,%1,%2,%3},{%4,%5,%6,%7},{%8,%9},{%0,%1,%2,%3};\n"
        : "+f"(d[0]), "+f"(d[1]), "+f"(d[2]), "+f"(d[3])
        : "r"(a0), "r"(a1), "r"(a2), "r"(a3), "r"(b0), "r"(b1));
}

// ---------------- prep: copy h, zero agg, radial (one launch) ------------------
__global__ void k_prep(const float* __restrict__ h, const float* __restrict__ coords,
                       const int* __restrict__ edges) {
    int i = blockIdx.x * blockDim.x + threadIdx.x;   // 640000 threads
    ((float4*)g_h)[i] = ((const float4*)h)[i];
    ((float4*)g_agg)[i] = make_float4(0.f, 0.f, 0.f, 0.f);
    if (i < NE) {
        int r = edges[i], c = edges[NE + i];
        float dx = coords[3 * r]     - coords[3 * c];
        float dy = coords[3 * r + 1] - coords[3 * c + 1];
        float dz = coords[3 * r + 2] - coords[3 * c + 2];
        g_radial[i] = dx * dx + dy * dy + dz * dz;
    }
}

// convert weights: tf32 copies for k_pq/k_node; fp16 transposed/permuted for k_edge
__global__ void k_cvt_all(const float* __restrict__ ew1, const float* __restrict__ ew2,
                          const float* __restrict__ nw1, const float* __restrict__ nw2) {
    int t0 = blockIdx.x * blockDim.x + threadIdx.x;
    int stride = gridDim.x * blockDim.x;
    for (int i = t0; i < NL * 289 * H; i += stride) g_ew1t[i] = tf32r(ew1[i]);
    for (int i = t0; i < NL * 2 * H * H; i += stride) g_nw1t[i] = tf32r(nw1[i]);
    for (int i = t0; i < NL * H * H; i += stride)   g_nw2t[i] = tf32r(nw2[i]);
    // W1c fp16: [lyr][n][k48], k: 0..31 = ew1 rows 257+k, 32 = row 256 (radial), 33..47 = 0
    for (int i = t0; i < NL * 128 * 48; i += stride) {
        int lyr = i / (128 * 48), rem = i % (128 * 48);
        int n = rem / 48, k = rem % 48;
        float v = (k < 32) ? ew1[((size_t)lyr * 289 + 257 + k) * H + n]
                : (k == 32) ? ew1[((size_t)lyr * 289 + 256) * H + n] : 0.f;
        g_w1ch[lyr * 128 * 48 + n * 48 + kperm(k)] = __float2half_rn(v);
    }
    // W2 fp16: [lyr][n][k128] permuted
    for (int i = t0; i < NL * 128 * 128; i += stride) {
        int lyr = i >> 14, rem = i & 16383;
        int n = rem >> 7, k = rem & 127;
        g_w2h[(lyr << 14) + (n << 7) + kperm(k)] =
            __float2half_rn(ew2[((size_t)lyr * H + k) * H + n]);
    }
}

// ---------------- k_pq: P = h @ W1a, Q = h @ W1b (tf32 mma) -------------------
#define PQ_SMEM ((64 * 132 + 128 * 132) * 4)
__global__ __launch_bounds__(256) void k_pq(int lyr) {
    extern __shared__ float sm[];
    float* As = sm;                 // [64][132]
    float* Bs = sm + 64 * 132;      // [128][132]
    int tid = threadIdx.x;
    int m0 = blockIdx.x * 64;
    const float* B = g_ew1t + (size_t)lyr * 289 * H + (size_t)blockIdx.y * H * H;
    float* C = blockIdx.y ? g_Q : g_P;

#pragma unroll
    for (int i = 0; i < 8; i++) {
        int id = tid + 256 * i;
        int r = id >> 5, cv = id & 31;
        int n = m0 + r;
        float4 v = (n < NN) ? ((const float4*)(g_h + (size_t)n * H))[cv]
                            : make_float4(0.f, 0.f, 0.f, 0.f);
        v.x = tf32r(v.x); v.y = tf32r(v.y); v.z = tf32r(v.z); v.w = tf32r(v.w);
        ((float4*)(As + r * 132))[cv] = v;
    }
#pragma unroll
    for (int i = 0; i < 16; i++) {
        int id = tid + 256 * i;
        int r = id >> 5, cv = id & 31;
        ((float4*)(Bs + r * 132))[cv] = ((const float4*)(B + (size_t)r * H))[cv];
    }
    __syncthreads();

    int wid = tid >> 5, lane = tid & 31;
    int warpM = wid & 3, warpN = wid >> 2;
    int g = lane >> 2, t = lane & 3;
    int r0 = warpM * 16, n0 = warpN * 64;
    const float* A0 = As + (r0 + g) * 132;
    const float* A1 = As + (r0 + g + 8) * 132;
    const float* Bp = Bs + t * 132 + n0 + g;

    float acc[8][4];
#pragma unroll
    for (int nf = 0; nf < 8; nf++)
#pragma unroll
        for (int j = 0; j < 4; j++) acc[nf][j] = 0.f;

#pragma unroll
    for (int k0 = 0; k0 < 128; k0 += 8) {
        unsigned int a0 = fb(A0[k0 + t]),     a1 = fb(A1[k0 + t]);
        unsigned int a2 = fb(A0[k0 + t + 4]), a3 = fb(A1[k0 + t + 4]);
#pragma unroll
        for (int nf = 0; nf < 8; nf++) {
            unsigned int b0 = fb(Bp[k0 * 132 + nf * 8]);
            unsigned int b1 = fb(Bp[(k0 + 4) * 132 + nf * 8]);
            mma8(acc[nf], a0, a1, a2, a3, b0, b1);
        }
    }
    int ng  = m0 + r0 + g;
    int ng8 = ng + 8;
#pragma unroll
    for (int nf = 0; nf < 8; nf++) {
        int col = n0 + nf * 8 + 2 * t;
        if (ng < NN)
            *(float2*)(C + (size_t)ng * H + col)  = make_float2(acc[nf][0], acc[nf][1]);
        if (ng8 < NN)
            *(float2*)(C + (size_t)ng8 * H + col) = make_float2(acc[nf][2], acc[nf][3]);
    }
}

// ---------------- k_edge: persistent, fp16 m16n8k16 ---------------------------
// 148 blocks x 512 threads; tiles of 128 edges.
// X = [edge_attr(32) | radial | 0-pad] to K=48 (fp16); W1c/W2 n-major fp16 with
// k-pair permutation so each lane's B fragment is a single uint2 load.
#define EDGE_SMEM ((128 * 56 + 128 * 56 + 128 * 136 + 128 * 136) * 2 + 2 * ETILE * 4)

__global__ __launch_bounds__(512, 1) void k_edge(
    const int* __restrict__ edges, const float* __restrict__ edge_attr,
    const float* __restrict__ eb1, const float* __restrict__ eb2, int lyr) {
    extern __shared__ char smc[];
    __half* xs   = (__half*)smc;                    // [128][56]
    __half* W1cs = xs + 128 * 56;                   // [128][56]  n-major perm
    __half* Sh   = W1cs + 128 * 56;                 // [128][136] m-major
    __half* W2s  = Sh + 128 * 136;                  // [128][136] n-major perm
    int*    rs   = (int*)(W2s + 128 * 136);         // [128]
    int*    cs   = rs + ETILE;

    int tid = threadIdx.x;

    // ---- stage W1c and W2 once per block (coalesced uint4 row copies)
    {
        const uint4* s1 = (const uint4*)(g_w1ch + (size_t)lyr * 128 * 48);
        for (int i = tid; i < 128 * 6; i += 512) {          // 6 uint4 per 48-half row
            int r = i / 6, c = i % 6;
            ((uint4*)(W1cs + r * 56))[c] = s1[i];
        }
        const uint4* s2 = (const uint4*)(g_w2h + ((size_t)lyr << 14));
        for (int i = tid; i < 128 * 16; i += 512) {         // 16 uint4 per 128-half row
            int r = i >> 4, c = i & 15;
            ((uint4*)(W2s + r * 136))[c] = s2[i];
        }
        // zero X pad halves k=33..47 once
        if (tid < 128) {
            __half* xr = xs + tid * 56;
#pragma unroll
            for (int j = 33; j < 48; j++) xr[j] = __float2half_rn(0.f);
        }
    }

    int wid = tid >> 5, lane = tid & 31;
    int warpM = wid & 7, warpN = wid >> 3;          // 8 M-groups x 2 N-groups
    int g = lane >> 2, t = lane & 3;
    int r0 = warpM * 16, n0 = warpN * 64;

    for (int tile = blockIdx.x; tile < NTILES; tile += gridDim.x) {
        int e0 = tile * ETILE;
        __syncthreads();   // prior tile's phase2 reads / phase3 rs reads done

        // ---- stage X for this tile
        if (tid < ETILE) {
            rs[tid] = edges[e0 + tid];
            cs[tid] = edges[NE + e0 + tid];
            xs[tid * 56 + 32] = __float2half_rn(g_radial[e0 + tid]);
        }
#pragma unroll
        for (int i = 0; i < 2; i++) {               // edge_attr: 128 x 8 float4 -> k 0..31
            int id = tid + 512 * i;
            int e = id >> 3, cv = id & 7;
            float4 v = ((const float4*)(edge_attr + (size_t)(e0 + e) * DE))[cv];
            __half2* xp = (__half2*)(xs + e * 56 + cv * 4);
            xp[0] = __floats2half2_rn(v.x, v.y);
            xp[1] = __floats2half2_rn(v.z, v.w);
        }
        __syncthreads();

        // ---- phase 1: X @ W1c (K=48, fp16) + bias + P/Q gathers + silu -> Sh
        {
            float acc[8][4];
#pragma unroll
            for (int nf = 0; nf < 8; nf++) {
                float2 b = *(const float2*)(eb1 + n0 + nf * 8 + 2 * t);
                acc[nf][0] = b.x; acc[nf][1] = b.y; acc[nf][2] = b.x; acc[nf][3] = b.y;
            }
            const __half* A0h = xs + (r0 + g) * 56;
            const __half* A1h = A0h + 8 * 56;
#pragma unroll
            for (int k0 = 0; k0 < 48; k0 += 16) {
                unsigned int a0 = *(const unsigned int*)(A0h + k0 + 2 * t);
                unsigned int a1 = *(const unsigned int*)(A1h + k0 + 2 * t);
                unsigned int a2 = *(const unsigned int*)(A0h + k0 + 8 + 2 * t);
                unsigned int a3 = *(const unsigned int*)(A1h + k0 + 8 + 2 * t);
#pragma unroll
                for (int nf = 0; nf < 8; nf++) {
                    uint2 bb = *(const uint2*)(W1cs + (n0 + nf * 8 + g) * 56 + k0 + 4 * t);
                    mma16(acc[nf], a0, a1, a2, a3, bb.x, bb.y);
                }
            }
            int rA = rs[r0 + g], rB = rs[r0 + g + 8];
            int cA = cs[r0 + g], cB = cs[r0 + g + 8];
            const float* PA = g_P + (size_t)rA * H;
            const float* QA = g_Q + (size_t)cA * H;
            const float* PB = g_P + (size_t)rB * H;
            const float* QB = g_Q + (size_t)cB * H;
            __half* S0 = Sh + (r0 + g) * 136;
            __half* S1 = S0 + 8 * 136;
#pragma unroll
            for (int nf = 0; nf < 8; nf++) {
                int col = n0 + nf * 8 + 2 * t;
                float2 pa = *(const float2*)(PA + col), qa = *(const float2*)(QA + col);
                float2 pb = *(const float2*)(PB + col), qb = *(const float2*)(QB + col);
                float v0 = acc[nf][0] + pa.x + qa.x;
                float v1 = acc[nf][1] + pa.y + qa.y;
                float v2 = acc[nf][2] + pb.x + qb.x;
                float v3 = acc[nf][3] + pb.y + qb.y;
                *(__half2*)(S0 + col) = __floats2half2_rn(siluf(v0), siluf(v1));
                *(__half2*)(S1 + col) = __floats2half2_rn(siluf(v2), siluf(v3));
            }
        }
        __syncthreads();

        // ---- phase 2: Sh @ W2 (K=128, fp16)
        float acc2[8][4];
#pragma unroll
        for (int nf = 0; nf < 8; nf++)
#pragma unroll
            for (int j = 0; j < 4; j++) acc2[nf][j] = 0.f;
        {
            const __half* A0s = Sh + (r0 + g) * 136;
            const __half* A1s = A0s + 8 * 136;
#pragma unroll
            for (int k0 = 0; k0 < 128; k0 += 16) {
                unsigned int a0 = *(const unsigned int*)(A0s + k0 + 2 * t);
                unsigned int a1 = *(const unsigned int*)(A1s + k0 + 2 * t);
                unsigned int a2 = *(const unsigned int*)(A0s + k0 + 8 + 2 * t);
                unsigned int a3 = *(const unsigned int*)(A1s + k0 + 8 + 2 * t);
#pragma unroll
                for (int nf = 0; nf < 8; nf++) {
                    uint2 bb = *(const uint2*)(W2s + (n0 + nf * 8 + g) * 136 + k0 + 4 * t);
                    mma16(acc2[nf], a0, a1, a2, a3, bb.x, bb.y);
                }
            }
        }

        // ---- phase 3: pack via shfl, bias+silu, float4 atomic scatter
        {
            bool odd = (t & 1);
            int node = odd ? rs[r0 + g + 8] : rs[r0 + g];
#pragma unroll
            for (int nf = 0; nf < 8; nf++) {
                float px = odd ? acc2[nf][0] : acc2[nf][2];
                float py = odd ? acc2[nf][1] : acc2[nf][3];
                float rx = __shfl_xor_sync(0xffffffffu, px, 1);
                float ry = __shfl_xor_sync(0xffffffffu, py, 1);
                float4 v;
                int col;
                if (!odd) {
                    v = make_float4(acc2[nf][0], acc2[nf][1], rx, ry);
                    col = n0 + nf * 8 + 2 * t;
                } else {
                    v = make_float4(rx, ry, acc2[nf][2], acc2[nf][3]);
                    col = n0 + nf * 8 + 2 * (t - 1);
                }
                float4 b = *(const float4*)(eb2 + col);
                v = silu4(add4(v, b));
                atomicAdd((float4*)(g_agg + (size_t)node * H + col), v);
            }
        }
    }
}

// ---------------- k_node: fused [h|agg]@nw1 -> silu -> @nw2 (+res) + agg-zero --
#define NODE_SMEM ((64 * 260 + 256 * 132) * 4)
__global__ __launch_bounds__(256) void k_node(
    const float* __restrict__ nb1, const float* __restrict__ nb2,
    int lyr, int residual) {
    extern __shared__ float sm[];
    float* As  = sm;                  // [64][260]; later Ss [64][132]
    float* Bs  = sm + 64 * 260;       // [256][132] nw1t; later [128][132] nw2t
    int tid = threadIdx.x;
    int m0 = blockIdx.x * 64;

#pragma unroll
    for (int i = 0; i < 16; i++) {
        int id = tid + 256 * i;
        int r = id >> 6, cv = id & 63;
        int n = m0 + r;
        const float* src = (cv < 32) ? (g_h + (size_t)n * H + cv * 4)
                                     : (g_agg + (size_t)n * H + (cv - 32) * 4);
        float4 v = (n < NN) ? *(const float4*)src : make_float4(0.f, 0.f, 0.f, 0.f);
        if (cv >= 32 && n < NN)
            *(float4*)(g_agg + (size_t)n * H + (cv - 32) * 4) = make_float4(0.f, 0.f, 0.f, 0.f);
        v.x = tf32r(v.x); v.y = tf32r(v.y); v.z = tf32r(v.z); v.w = tf32r(v.w);
        float* dst = As + r * 260 + cv * 4;
        dst[0] = v.x; dst[1] = v.y; dst[2] = v.z; dst[3] = v.w;
    }
    {
        const float* B = g_nw1t + (size_t)lyr * 2 * H * H;
#pragma unroll
        for (int i = 0; i < 32; i++) {
            int id = tid + 256 * i;
            int r = id >> 5, cv = id & 31;
            ((float4*)(Bs + r * 132))[cv] = ((const float4*)(B + (size_t)r * H))[cv];
        }
    }
    __syncthreads();

    int wid = tid >> 5, lane = tid & 31;
    int warpM = wid & 3, warpN = wid >> 2;
    int g = lane >> 2, t = lane & 3;
    int r0 = warpM * 16, n0 = warpN * 64;

    float acc[8][4];
#pragma unroll
    for (int nf = 0; nf < 8; nf++)
#pragma unroll
        for (int j = 0; j < 4; j++) acc[nf][j] = 0.f;

    {   // GEMM1: K = 256
        const float* A0 = As + (r0 + g) * 260;
        const float* A1 = As + (r0 + g + 8) * 260;
        const float* Bp = Bs + t * 132 + n0 + g;
#pragma unroll
        for (int k0 = 0; k0 < 256; k0 += 8) {
            unsigned int a0 = fb(A0[k0 + t]),     a1 = fb(A1[k0 + t]);
            unsigned int a2 = fb(A0[k0 + t + 4]), a3 = fb(A1[k0 + t + 4]);
#pragma unroll
            for (int nf = 0; nf < 8; nf++) {
                unsigned int b0 = fb(Bp[k0 * 132 + nf * 8]);
                unsigned int b1 = fb(Bp[(k0 + 4) * 132 + nf * 8]);
                mma8(acc[nf], a0, a1, a2, a3, b0, b1);
            }
        }
    }
    __syncthreads();

    {   // epilogue 1: silu(+b1) -> Ss (tf32), load Bs2
        float* Ss = As;
#pragma unroll
        for (int nf = 0; nf < 8; nf++) {
            int col = n0 + nf * 8 + 2 * t;
            float2 b = *(const float2*)(nb1 + col);
            float* s0 = Ss + (r0 + g) * 132 + col;
            float* s1 = Ss + (r0 + g + 8) * 132 + col;
            s0[0] = tf32r(siluf(acc[nf][0] + b.x));
            s0[1] = tf32r(siluf(acc[nf][1] + b.y));
            s1[0] = tf32r(siluf(acc[nf][2] + b.x));
            s1[1] = tf32r(siluf(acc[nf][3] + b.y));
        }
        const float* B = g_nw2t + (size_t)lyr * H * H;
#pragma unroll
        for (int i = 0; i < 16; i++) {
            int id = tid + 256 * i;
            int r = id >> 5, cv = id & 31;
            ((float4*)(Bs + r * 132))[cv] = ((const float4*)(B + (size_t)r * H))[cv];
        }
    }
    __syncthreads();

    {   // GEMM2: K = 128
#pragma unroll
        for (int nf = 0; nf < 8; nf++)
#pragma unroll
            for (int j = 0; j < 4; j++) acc[nf][j] = 0.f;
        const float* Ss = As;
        const float* A0 = Ss + (r0 + g) * 132;
        const float* A1 = Ss + (r0 + g + 8) * 132;
        const float* Bp = Bs + t * 132 + n0 + g;
#pragma unroll
        for (int k0 = 0; k0 < 128; k0 += 8) {
            unsigned int a0 = fb(A0[k0 + t]),     a1 = fb(A1[k0 + t]);
            unsigned int a2 = fb(A0[k0 + t + 4]), a3 = fb(A1[k0 + t + 4]);
#pragma unroll
            for (int nf = 0; nf < 8; nf++) {
                unsigned int b0 = fb(Bp[k0 * 132 + nf * 8]);
                unsigned int b1 = fb(Bp[(k0 + 4) * 132 + nf * 8]);
                mma8(acc[nf], a0, a1, a2, a3, b0, b1);
            }
        }
    }

    int ng  = m0 + r0 + g;
    int ng8 = ng + 8;
#pragma unroll
    for (int nf = 0; nf < 8; nf++) {
        int col = n0 + nf * 8 + 2 * t;
        float2 b = *(const float2*)(nb2 + col);
        if (ng < NN) {
            float2* hp = (float2*)(g_h + (size_t)ng * H + col);
            float2 o = make_float2(acc[nf][0] + b.x, acc[nf][1] + b.y);
            if (residual) { float2 old = *hp; o.x += old.x; o.y += old.y; }
            *hp = o;
        }
        if (ng8 < NN) {
            float2* hp = (float2*)(g_h + (size_t)ng8 * H + col);
            float2 o = make_float2(acc[nf][2] + b.x, acc[nf][3] + b.y);
            if (residual) { float2 old = *hp; o.x += old.x; o.y += old.y; }
            *hp = o;
        }
    }
}

// ---------------- final LayerNorm ---------------------------------------------
__global__ void k_ln(const float* __restrict__ gam, const float* __restrict__ bet,
                     float* __restrict__ out) {
    int gw = (blockIdx.x * blockDim.x + threadIdx.x) >> 5;
    int lane = threadIdx.x & 31;
    if (gw >= NN) return;
    const float* hr = g_h + (size_t)gw * H;
    float v[4];
    float s = 0.f;
#pragma unroll
    for (int j = 0; j < 4; j++) { v[j] = hr[lane + 32 * j]; s += v[j]; }
#pragma unroll
    for (int o = 16; o > 0; o >>= 1) s += __shfl_xor_sync(0xffffffffu, s, o);
    float mu = s * (1.f / 128.f);
    float vs = 0.f;
#pragma unroll
    for (int j = 0; j < 4; j++) { float d = v[j] - mu; vs += d * d; }
#pragma unroll
    for (int o = 16; o > 0; o >>= 1) vs += __shfl_xor_sync(0xffffffffu, vs, o);
    float inv = rsqrtf(vs * (1.f / 128.f) + 1e-5f);
#pragma unroll
    for (int j = 0; j < 4; j++) {
        int f = lane + 32 * j;
        out[(size_t)gw * H + f] = (v[j] - mu) * inv * gam[f] + bet[f];
    }
}

// ---------------- launch -------------------------------------------------------
extern "C" void kernel_launch(void* const* d_in, const int* in_sizes, int n_in,
                              void* d_out, int out_size) {
    const float* h   = (const float*)d_in[0];
    const float* co  = (const float*)d_in[1];
    const float* ea  = (const float*)d_in[2];
    const int*   ed  = (const int*)d_in[3];
    const float* ew1 = (const float*)d_in[4];
    const float* eb1 = (const float*)d_in[5];
    const float* ew2 = (const float*)d_in[6];
    const float* eb2 = (const float*)d_in[7];
    const float* nw1 = (const float*)d_in[8];
    const float* nb1 = (const float*)d_in[9];
    const float* nw2 = (const float*)d_in[10];
    const float* nb2 = (const float*)d_in[11];
    const float* lng = (const float*)d_in[12];
    const float* lnb = (const float*)d_in[13];
    float* out = (float*)d_out;

    cudaFuncSetAttribute(k_pq,   cudaFuncAttributeMaxDynamicSharedMemorySize, PQ_SMEM);
    cudaFuncSetAttribute(k_edge, cudaFuncAttributeMaxDynamicSharedMemorySize, EDGE_SMEM);
    cudaFuncSetAttribute(k_node, cudaFuncAttributeMaxDynamicSharedMemorySize, NODE_SMEM);

    k_prep<<<2500, 256>>>(h, co, ed);
    k_cvt_all<<<256, 512>>>(ew1, ew2, nw1, nw2);

    for (int i = 0; i < NL; i++) {
        k_pq<<<dim3(313, 2), 256, PQ_SMEM>>>(i);
        k_edge<<<148, 512, EDGE_SMEM>>>(ed, ea, eb1 + i * H, eb2 + i * H, i);
        k_node<<<313, 256, NODE_SMEM>>>(nb1 + i * H, nb2 + i * H, i, i > 0);
    }
    k_ln<<<2500, 256>>>(lng, lnb, out);
}